// round 14
// baseline (speedup 1.0000x reference)
#include <cuda_runtime.h>
#include <cuda_bf16.h>
#include <cstdint>

// Problem constants
#define BATCH 32
#define NN    512       // nodes
#define NF    128       // input features
#define FH    64        // hidden per head
#define NH    8         // heads
#define NC    16        // classes
#define BH    (BATCH*NH)

// ------------------------- scratch (device globals, no allocs) -------------
__device__ float    g_h[BATCH*NH*NN*FH];     // head projections [b][h][n][64]
__device__ float    g_f1[BATCH*NH*NN];
__device__ float    g_f2[BATCH*NH*NN];
__device__ unsigned g_adjbits[BATCH*NN*16];  // 512 bits per row
__device__ float    g_xcat[BATCH*NN*NH*FH];  // layer-1 output [b][n][512]
__device__ float    g_h2[BATCH*NN*NC];       // output projection
__device__ float    g_f1o[BATCH*NN];
__device__ float    g_f2o[BATCH*NN];

// ------------------------- helpers -----------------------------------------
__device__ __forceinline__ float to_tf32(float v) {
    uint32_t b;
    asm("cvt.rna.tf32.f32 %0, %1;" : "=r"(b) : "f"(v));
    return __uint_as_float(b);
}
__device__ __forceinline__ uint32_t tf32_bits(float v) {
    uint32_t b;
    asm("cvt.rna.tf32.f32 %0, %1;" : "=r"(b) : "f"(v));
    return b;
}

__device__ __forceinline__ void mma_tf32(float d[4], const uint32_t a[4], const uint32_t b[2]) {
    asm volatile(
        "mma.sync.aligned.m16n8k8.row.col.f32.tf32.tf32.f32 "
        "{%0,%1,%2,%3}, {%4,%5,%6,%7}, {%8,%9}, {%0,%1,%2,%3};"
        : "+f"(d[0]), "+f"(d[1]), "+f"(d[2]), "+f"(d[3])
        : "r"(a[0]), "r"(a[1]), "r"(a[2]), "r"(a[3]), "r"(b[0]), "r"(b[1]));
}

__device__ __forceinline__ void cp_async16(uint32_t saddr, const void* g) {
    asm volatile("cp.async.cg.shared.global [%0], [%1], 16;" :: "r"(saddr), "l"(g));
}
#define CP_COMMIT() asm volatile("cp.async.commit_group;" ::: "memory")
#define CP_WAIT(n)  asm volatile("cp.async.wait_group %0;" :: "n"(n) : "memory")

// ------------------------- kernel 1: adjacency -> bitmask ------------------
__global__ void adjbits_kernel(const int* __restrict__ adj) {
    int w = threadIdx.x >> 5, lane = threadIdx.x & 31;
    int row = blockIdx.x * 8 + w;
    const int* ap = adj + (size_t)row * NN;
    unsigned* op = g_adjbits + row * 16;
#pragma unroll
    for (int it = 0; it < 16; ++it) {
        int v = ap[it * 32 + lane];
        unsigned m = __ballot_sync(0xffffffffu, v > 0);
        if (lane == 0) op[it] = m;
    }
}

// ------------------------- kernel 2: head GEMM (x resident, W pipelined) ---
#define XS_STRIDE 136
#define WS_STRIDE 72
#define GH_WS_OFF  (64*XS_STRIDE)                  // floats
#define GH_RED_OFF (GH_WS_OFF + 2*128*WS_STRIDE)   // floats
#define GH_SMEM ((GH_RED_OFF + 256) * 4)

__global__ void __launch_bounds__(256) gemm_heads(const float* __restrict__ x,
                                                  const float* __restrict__ Wh,
                                                  const float* __restrict__ a1,
                                                  const float* __restrict__ a2) {
    extern __shared__ float sm[];
    float* xs = sm;                    // [64][136] raw fp32
    float* Wsb[2] = { sm + GH_WS_OFF, sm + GH_WS_OFF + 128 * WS_STRIDE };
    float* sred = sm + GH_RED_OFF;     // [64][2 nt-halves][2]
    int b = blockIdx.y;
    int n0 = blockIdx.x * 64;
    int t = threadIdx.x;
    uint32_t xs_u  = (uint32_t)__cvta_generic_to_shared(xs);
    uint32_t ws_u[2] = { (uint32_t)__cvta_generic_to_shared(Wsb[0]),
                         (uint32_t)__cvta_generic_to_shared(Wsb[1]) };

    // group0: x tile + W(head 0)
    const float4* xp4 = (const float4*)(x + ((size_t)b * NN + n0) * NF);
    for (int idx = t; idx < 64 * 32; idx += 256) {
        int r = idx >> 5, c4 = idx & 31;
        cp_async16(xs_u + (r * XS_STRIDE + c4 * 4) * 4, xp4 + idx);
    }
    const float4* Wp4 = (const float4*)Wh;   // [NH][128][16] float4
    for (int idx = t; idx < 128 * 16; idx += 256) {
        int f = idx >> 4, o4 = idx & 15;
        cp_async16(ws_u[0] + (f * WS_STRIDE + o4 * 4) * 4, Wp4 + idx);
    }
    CP_COMMIT();

    int w = t >> 5, lane = t & 31;
    int gid = lane >> 2, tig = lane & 3;
    int mt = w >> 1;
    int nbase = (w & 1) * 32;

#pragma unroll 1
    for (int head = 0; head < NH; ++head) {
        int buf = head & 1;
        if (head < NH - 1) {
            const float4* Wn = Wp4 + (size_t)(head + 1) * 128 * 16;
            for (int idx = t; idx < 128 * 16; idx += 256) {
                int f = idx >> 4, o4 = idx & 15;
                cp_async16(ws_u[buf ^ 1] + (f * WS_STRIDE + o4 * 4) * 4, Wn + idx);
            }
            CP_COMMIT();
            CP_WAIT(1);
        } else {
            CP_WAIT(0);
        }
        __syncthreads();

        const float* Ws = Wsb[buf];
        float d[4][4] = {};
        uint32_t a[4], bf[2];
#pragma unroll
        for (int kk = 0; kk < 16; ++kk) {
            int k0 = kk * 8;
            const float* pa = xs + (mt * 16 + gid) * XS_STRIDE + k0 + tig;
            a[0] = tf32_bits(pa[0]);
            a[1] = tf32_bits(pa[8 * XS_STRIDE]);
            a[2] = tf32_bits(pa[4]);
            a[3] = tf32_bits(pa[8 * XS_STRIDE + 4]);
#pragma unroll
            for (int nt = 0; nt < 4; ++nt) {
                const float* pb = Ws + (k0 + tig) * WS_STRIDE + nbase + nt * 8 + gid;
                bf[0] = tf32_bits(pb[0]);
                bf[1] = tf32_bits(pb[4 * WS_STRIDE]);
                mma_tf32(d[nt], a, bf);
            }
        }
        float* hp = g_h + (((size_t)b * NH + head) * NN + n0) * FH;
#pragma unroll
        for (int nt = 0; nt < 4; ++nt) {
            int col = nbase + nt * 8 + 2 * tig;
            int r0 = mt * 16 + gid;
            *(float2*)&hp[r0 * FH + col]       = make_float2(d[nt][0], d[nt][1]);
            *(float2*)&hp[(r0 + 8) * FH + col] = make_float2(d[nt][2], d[nt][3]);
        }

        // fused f1/f2
        float s1a = 0.f, s1b = 0.f, s2a = 0.f, s2b = 0.f;
#pragma unroll
        for (int nt = 0; nt < 4; ++nt) {
            int c0 = nbase + nt * 8 + 2 * tig;
            float a1x = __ldg(&a1[head * FH + c0]), a1y = __ldg(&a1[head * FH + c0 + 1]);
            float a2x = __ldg(&a2[head * FH + c0]), a2y = __ldg(&a2[head * FH + c0 + 1]);
            s1a += d[nt][0] * a1x + d[nt][1] * a1y;
            s1b += d[nt][2] * a1x + d[nt][3] * a1y;
            s2a += d[nt][0] * a2x + d[nt][1] * a2y;
            s2b += d[nt][2] * a2x + d[nt][3] * a2y;
        }
#pragma unroll
        for (int o = 1; o <= 2; o <<= 1) {
            s1a += __shfl_xor_sync(0xffffffffu, s1a, o);
            s1b += __shfl_xor_sync(0xffffffffu, s1b, o);
            s2a += __shfl_xor_sync(0xffffffffu, s2a, o);
            s2b += __shfl_xor_sync(0xffffffffu, s2b, o);
        }
        if (tig == 0) {
            int rl = mt * 16 + gid, hh = w & 1;
            sred[(rl)     * 4 + hh * 2 + 0] = s1a;
            sred[(rl)     * 4 + hh * 2 + 1] = s2a;
            sred[(rl + 8) * 4 + hh * 2 + 0] = s1b;
            sred[(rl + 8) * 4 + hh * 2 + 1] = s2b;
        }
        __syncthreads();
        if (t < 64) {
            int gi = (b * NH + head) * NN + n0 + t;
            g_f1[gi] = sred[t * 4 + 0] + sred[t * 4 + 2];
            g_f2[gi] = sred[t * 4 + 1] + sred[t * 4 + 3];
        }
    }
}

// ------------------------- kernel 3: attn layer 1 (register-P, 512 thr) ----
// fp32/tf32 h in smem (conflict-free B frags). Raw-fp32 P fragments (HW
// tf32 truncation). Rowsums on the fma pipe (FADD + shfl) — the tensor
// pipe is the binding resource here, keep it for the real GEMM only.
#define HS_STRIDE 72
#define A1_F2Q  (NN*HS_STRIDE*4)            // 147456
#define ATTN1_SMEM (A1_F2Q + NN*16)         // 155648

__global__ void __launch_bounds__(512) attn1_kernel() {
    extern __shared__ __align__(16) char smc[];
    float*  hs  = (float*)smc;
    float4* f2q = (float4*)(smc + A1_F2Q);

    int t = threadIdx.x, w = t >> 5, lane = t & 31;
    int gid = lane >> 2, tig = lane & 3;
    int blk = blockIdx.x, b = blk >> 3, head = blk & 7;
    const float* hp  = g_h  + (size_t)blk * NN * FH;
    const float* f1p = g_f1 + blk * NN;
    const float* f2p = g_f2 + blk * NN;
    const unsigned* ab = g_adjbits + (size_t)b * NN * 16;

    {
        const float4* hp4 = (const float4*)hp;
        for (int idx = t; idx < NN * 16; idx += 512) {
            int j = idx >> 4, c0 = (idx & 15) * 4;
            float4 v = hp4[idx];
            v.x = to_tf32(v.x); v.y = to_tf32(v.y); v.z = to_tf32(v.z); v.w = to_tf32(v.w);
            *(float4*)&hs[j * HS_STRIDE + c0] = v;
        }
        for (int i = t; i < NN; i += 512) {
            float f2 = f2p[i];
            f2q[i] = make_float4(f2, __expf(f2), __expf(0.2f * f2), 0.f);
        }
    }
    __syncthreads();

#pragma unroll
    for (int iter = 0; iter < 2; ++iter) {
        int r0 = (iter * 16 + w) * 16;
        int ra = r0 + gid, rb = ra + 8;
        float f1a = __ldg(&f1p[ra]), f1b = __ldg(&f1p[rb]);
        float Ea = __expf(f1a), Ean = __expf(0.2f * f1a), nfa = -f1a;
        float Eb = __expf(f1b), Ebn = __expf(0.2f * f1b), nfb = -f1b;
        const unsigned* ma = &ab[(size_t)ra * 16];
        const unsigned* mb = &ab[(size_t)rb * 16];

        float d[8][4];
#pragma unroll
        for (int nt = 0; nt < 8; ++nt)
#pragma unroll
            for (int u = 0; u < 4; ++u) d[nt][u] = 0.f;
        float rs0 = 0.f, rs1 = 0.f;

        for (int kw = 0; kw < 16; ++kw) {
            unsigned wa = __ldg(&ma[kw]) >> tig;
            unsigned wb = __ldg(&mb[kw]) >> tig;
#pragma unroll
            for (int ks = 0; ks < 4; ++ks) {
                int k0 = kw * 32 + ks * 8;
                unsigned w0 = wa >> (ks * 8);
                unsigned w1 = wb >> (ks * 8);
                float4 q0 = f2q[k0 + tig];
                float4 q1 = f2q[k0 + tig + 4];

                float pa0 = (q0.x < nfa) ? Ean * q0.z : Ea * q0.y;
                pa0 = (w0 & 1u) ? pa0 : 0.f;
                float pb0 = (q0.x < nfb) ? Ebn * q0.z : Eb * q0.y;
                pb0 = (w1 & 1u) ? pb0 : 0.f;
                float pa1 = (q1.x < nfa) ? Ean * q1.z : Ea * q1.y;
                pa1 = ((w0 >> 4) & 1u) ? pa1 : 0.f;
                float pb1 = (q1.x < nfb) ? Ebn * q1.z : Eb * q1.y;
                pb1 = ((w1 >> 4) & 1u) ? pb1 : 0.f;

                rs0 += pa0 + pa1;
                rs1 += pb0 + pb1;

                uint32_t a[4];
                a[0] = __float_as_uint(pa0);
                a[1] = __float_as_uint(pb0);
                a[2] = __float_as_uint(pa1);
                a[3] = __float_as_uint(pb1);

                const float* pb = hs + (k0 + tig) * HS_STRIDE + gid;
#pragma unroll
                for (int nt = 0; nt < 8; ++nt) {
                    uint32_t bf[2];
                    bf[0] = __float_as_uint(pb[nt * 8]);
                    bf[1] = __float_as_uint(pb[4 * HS_STRIDE + nt * 8]);
                    mma_tf32(d[nt], a, bf);
                }
            }
        }

        rs0 += __shfl_xor_sync(0xffffffffu, rs0, 1);
        rs0 += __shfl_xor_sync(0xffffffffu, rs0, 2);
        rs1 += __shfl_xor_sync(0xffffffffu, rs1, 1);
        rs1 += __shfl_xor_sync(0xffffffffu, rs1, 2);
        float inv0 = 1.f / rs0, inv1 = 1.f / rs1;

        float* oa = g_xcat + ((size_t)b * NN + ra) * (NH * FH) + head * FH;
        float* ob = g_xcat + ((size_t)b * NN + rb) * (NH * FH) + head * FH;
#pragma unroll
        for (int nt = 0; nt < 8; ++nt) {
            float v0 = d[nt][0] * inv0, v1 = d[nt][1] * inv0;
            v0 = v0 > 0.f ? v0 : (__expf(v0) - 1.f);
            v1 = v1 > 0.f ? v1 : (__expf(v1) - 1.f);
            *(float2*)&oa[nt * 8 + 2 * tig] = make_float2(v0, v1);
            float v2 = d[nt][2] * inv1, v3 = d[nt][3] * inv1;
            v2 = v2 > 0.f ? v2 : (__expf(v2) - 1.f);
            v3 = v3 > 0.f ? v3 : (__expf(v3) - 1.f);
            *(float2*)&ob[nt * 8 + 2 * tig] = make_float2(v2, v3);
        }
    }
}

// ------------------------- kernel 4: output GEMM (3-buf pipeline) ----------
#define GO_WS_STRIDE 24
#define GO_XS_STRIDE 68
#define GO_XS_OFF  (512 * GO_WS_STRIDE)                       // floats
#define GO_RED_OFF (GO_XS_OFF + 3 * 64 * GO_XS_STRIDE)        // floats
#define GO_SMEM ((GO_RED_OFF + 256) * 4)

__global__ void __launch_bounds__(256) gemm_out(const float* __restrict__ Wout,
                                                const float* __restrict__ a1o,
                                                const float* __restrict__ a2o) {
    extern __shared__ float sm[];
    float* Ws = sm;                                   // [512][24]
    float* xsb[3] = { sm + GO_XS_OFF,
                      sm + GO_XS_OFF + 64 * GO_XS_STRIDE,
                      sm + GO_XS_OFF + 2 * 64 * GO_XS_STRIDE };
    float* sred = sm + GO_RED_OFF;
    int b = blockIdx.x, rt = blockIdx.y;
    int t = threadIdx.x, w = t >> 5, lane = t & 31;
    int gid = lane >> 2, tig = lane & 3;
    uint32_t ws_u = (uint32_t)__cvta_generic_to_shared(Ws);
    uint32_t xs_u[3] = { (uint32_t)__cvta_generic_to_shared(xsb[0]),
                         (uint32_t)__cvta_generic_to_shared(xsb[1]),
                         (uint32_t)__cvta_generic_to_shared(xsb[2]) };

    const float4* Wo4 = (const float4*)Wout;          // [512][4] float4
    const float4* xp4 = (const float4*)(g_xcat + ((size_t)b * NN + rt * 64) * 512);

    // group0: W + chunk0 ; group1: chunk1
    for (int idx = t; idx < 512 * 4; idx += 256) {
        int k = idx >> 2, c4 = idx & 3;
        cp_async16(ws_u + (k * GO_WS_STRIDE + c4 * 4) * 4, Wo4 + idx);
    }
    for (int idx = t; idx < 64 * 16; idx += 256) {
        int r = idx >> 4, c4 = idx & 15;
        cp_async16(xs_u[0] + (r * GO_XS_STRIDE + c4 * 4) * 4, xp4 + r * 128 + c4);
    }
    CP_COMMIT();
    for (int idx = t; idx < 64 * 16; idx += 256) {
        int r = idx >> 4, c4 = idx & 15;
        cp_async16(xs_u[1] + (r * GO_XS_STRIDE + c4 * 4) * 4, xp4 + r * 128 + 16 + c4);
    }
    CP_COMMIT();

    int mt = w >> 1, ntile = w & 1;
    float d[4] = {};
    uint32_t a[4], bf[2];

#pragma unroll 1
    for (int ch = 0; ch < 8; ++ch) {
        if (ch < 7) { CP_WAIT(1); } else { CP_WAIT(0); }
        __syncthreads();
        const float* xs = xsb[ch % 3];
#pragma unroll
        for (int ks = 0; ks < 8; ++ks) {
            int k0 = ks * 8;
            const float* pa = xs + (mt * 16 + gid) * GO_XS_STRIDE + k0 + tig;
            a[0] = tf32_bits(pa[0]);
            a[1] = tf32_bits(pa[8 * GO_XS_STRIDE]);
            a[2] = tf32_bits(pa[4]);
            a[3] = tf32_bits(pa[8 * GO_XS_STRIDE + 4]);
            const float* pb = Ws + (ch * 64 + k0 + tig) * GO_WS_STRIDE + ntile * 8 + gid;
            bf[0] = tf32_bits(pb[0]);
            bf[1] = tf32_bits(pb[4 * GO_WS_STRIDE]);
            mma_tf32(d, a, bf);
        }
        if (ch + 2 < 8) {
            int tb = (ch + 2) % 3;
            for (int idx = t; idx < 64 * 16; idx += 256) {
                int r = idx >> 4, c4 = idx & 15;
                cp_async16(xs_u[tb] + (r * GO_XS_STRIDE + c4 * 4) * 4,
                           xp4 + r * 128 + (ch + 2) * 16 + c4);
            }
            CP_COMMIT();
        }
    }

    // write h2 + fused f1o/f2o (cross-warp combine of the two n-tiles)
    int ra = rt * 64 + mt * 16 + gid, rb = ra + 8;
    int c0 = ntile * 8 + 2 * tig;
    *(float2*)&g_h2[((size_t)b * NN + ra) * NC + c0] = make_float2(d[0], d[1]);
    *(float2*)&g_h2[((size_t)b * NN + rb) * NC + c0] = make_float2(d[2], d[3]);

    float a1x = __ldg(&a1o[c0]), a1y = __ldg(&a1o[c0 + 1]);
    float a2x = __ldg(&a2o[c0]), a2y = __ldg(&a2o[c0 + 1]);
    float s1a = d[0] * a1x + d[1] * a1y;
    float s1b = d[2] * a1x + d[3] * a1y;
    float s2a = d[0] * a2x + d[1] * a2y;
    float s2b = d[2] * a2x + d[3] * a2y;
#pragma unroll
    for (int o = 1; o <= 2; o <<= 1) {
        s1a += __shfl_xor_sync(0xffffffffu, s1a, o);
        s1b += __shfl_xor_sync(0xffffffffu, s1b, o);
        s2a += __shfl_xor_sync(0xffffffffu, s2a, o);
        s2b += __shfl_xor_sync(0xffffffffu, s2b, o);
    }
    if (tig == 0) {
        int rl = mt * 16 + gid;
        sred[(rl)     * 4 + ntile * 2 + 0] = s1a;
        sred[(rl)     * 4 + ntile * 2 + 1] = s2a;
        sred[(rl + 8) * 4 + ntile * 2 + 0] = s1b;
        sred[(rl + 8) * 4 + ntile * 2 + 1] = s2b;
    }
    __syncthreads();
    if (t < 64) {
        g_f1o[b * NN + rt * 64 + t] = sred[t * 4 + 0] + sred[t * 4 + 2];
        g_f2o[b * NN + rt * 64 + t] = sred[t * 4 + 1] + sred[t * 4 + 3];
    }
}

// ------------------------- kernel 5: output attention (register-P MMA) -----
#define O_F2Q 32768
#define ATTN2_SMEM (O_F2Q + 8192)
__global__ void __launch_bounds__(256) attn_out(float* __restrict__ out_l2) {
    extern __shared__ __align__(16) char sm2[];
    float*  hs  = (float*)sm2;             // [512][16] swizzled
    float4* f2q = (float4*)(sm2 + O_F2Q);  // [512]

    int b = blockIdx.y, rbase = blockIdx.x * 128;
    const float* hp  = g_h2  + (size_t)b * NN * NC;
    const float* f1p = g_f1o + b * NN;
    const float* f2p = g_f2o + b * NN;
    const unsigned* ab = g_adjbits + (size_t)b * NN * 16;

    int t = threadIdx.x, w = t >> 5, lane = t & 31;
    int gid = lane >> 2, tig = lane & 3;

    for (int idx = t; idx < NN * NC; idx += 256) {
        int j = idx >> 4, c = idx & 15;
        hs[j * 16 + ((c + 4 * (j & 3)) & 15)] = to_tf32(hp[idx]);
    }
    for (int i = t; i < NN; i += 256) {
        float f2 = f2p[i];
        f2q[i] = make_float4(f2, __expf(f2), __expf(0.2f * f2), 0.f);
    }
    __syncthreads();

    const uint32_t ONE = 0x3f800000u;

    int ra = rbase + w * 16 + gid, rb = ra + 8;
    float f1a = __ldg(&f1p[ra]), f1b = __ldg(&f1p[rb]);
    float Ea = __expf(f1a), Ean = __expf(0.2f * f1a), nfa = -f1a;
    float Eb = __expf(f1b), Ebn = __expf(0.2f * f1b), nfb = -f1b;
    const unsigned* ma = &ab[(size_t)ra * 16];
    const unsigned* mb = &ab[(size_t)rb * 16];
    int c0 = (gid + 4 * tig) & 15;           // swizzled col for nt=0
    int c1 = (c0 + 8) & 15;                  // swizzled col for nt=1

    float d[3][4] = {};

    for (int kw = 0; kw < 16; ++kw) {
        unsigned wa = __ldg(&ma[kw]) >> tig;
        unsigned wb = __ldg(&mb[kw]) >> tig;
#pragma unroll
        for (int ks = 0; ks < 4; ++ks) {
            int k0 = kw * 32 + ks * 8;
            unsigned w0 = wa >> (ks * 8);
            unsigned w1 = wb >> (ks * 8);
            float4 q0 = f2q[k0 + tig];
            float4 q1 = f2q[k0 + tig + 4];

            float pa0 = (q0.x < nfa) ? Ean * q0.z : Ea * q0.y;
            pa0 = (w0 & 1u) ? pa0 : 0.f;
            float pb0 = (q0.x < nfb) ? Ebn * q0.z : Eb * q0.y;
            pb0 = (w1 & 1u) ? pb0 : 0.f;
            float pa1 = (q1.x < nfa) ? Ean * q1.z : Ea * q1.y;
            pa1 = ((w0 >> 4) & 1u) ? pa1 : 0.f;
            float pb1 = (q1.x < nfb) ? Ebn * q1.z : Eb * q1.y;
            pb1 = ((w1 >> 4) & 1u) ? pb1 : 0.f;

            uint32_t a[4];
            a[0] = __float_as_uint(pa0);
            a[1] = __float_as_uint(pb0);
            a[2] = __float_as_uint(pa1);
            a[3] = __float_as_uint(pb1);

            const float* pb0p = hs + (k0 + tig) * 16;
            const float* pb1p = hs + (k0 + tig + 4) * 16;
            uint32_t bf[2];
            bf[0] = __float_as_uint(pb0p[c0]);
            bf[1] = __float_as_uint(pb1p[c0]);
            mma_tf32(d[0], a, bf);
            bf[0] = __float_as_uint(pb0p[c1]);
            bf[1] = __float_as_uint(pb1p[c1]);
            mma_tf32(d[1], a, bf);
            bf[0] = ONE; bf[1] = ONE;
            mma_tf32(d[2], a, bf);
        }
    }

    float inv0 = 1.f / d[2][0], inv1 = 1.f / d[2][2];

    float* oa = out_l2 + ((size_t)b * NN + ra) * NC;
    float* ob = out_l2 + ((size_t)b * NN + rb) * NC;
#pragma unroll
    for (int nt = 0; nt < 2; ++nt) {
        *(float2*)&oa[nt * 8 + 2 * tig] = make_float2(d[nt][0] * inv0, d[nt][1] * inv0);
        *(float2*)&ob[nt * 8 + 2 * tig] = make_float2(d[nt][2] * inv1, d[nt][3] * inv1);
    }
}

// ------------------------- launch ------------------------------------------
extern "C" void kernel_launch(void* const* d_in, const int* in_sizes, int n_in,
                              void* d_out, int out_size) {
    const float* x    = (const float*)d_in[0];
    const int*   adj  = (const int*)  d_in[1];
    const float* Wh   = (const float*)d_in[2];
    const float* a1h  = (const float*)d_in[3];
    const float* a2h  = (const float*)d_in[4];
    const float* Wout = (const float*)d_in[5];
    const float* a1o  = (const float*)d_in[6];
    const float* a2o  = (const float*)d_in[7];
    float* out = (float*)d_out;

    cudaFuncSetAttribute(gemm_heads, cudaFuncAttributeMaxDynamicSharedMemorySize, GH_SMEM);
    cudaFuncSetAttribute(attn1_kernel, cudaFuncAttributeMaxDynamicSharedMemorySize, ATTN1_SMEM);
    cudaFuncSetAttribute(gemm_out, cudaFuncAttributeMaxDynamicSharedMemorySize, GO_SMEM);
    cudaFuncSetAttribute(attn_out, cudaFuncAttributeMaxDynamicSharedMemorySize, ATTN2_SMEM);

    adjbits_kernel<<<BATCH * NN / 8, 256>>>(adj);
    gemm_heads<<<dim3(8, BATCH), 256, GH_SMEM>>>(x, Wh, a1h, a2h);
    attn1_kernel<<<BH, 512, ATTN1_SMEM>>>();
    gemm_out<<<dim3(BATCH, 8), 256, GO_SMEM>>>(Wout, a1o, a2o);
    attn_out<<<dim3(4, BATCH), 256, ATTN2_SMEM>>>(out);
}

// round 15
// speedup vs baseline: 1.2665x; 1.2665x over previous
#include <cuda_runtime.h>
#include <cuda_bf16.h>
#include <cstdint>

// Problem constants
#define BATCH 32
#define NN    512       // nodes
#define NF    128       // input features
#define FH    64        // hidden per head
#define NH    8         // heads
#define NC    16        // classes
#define BH    (BATCH*NH)

// ------------------------- scratch (device globals, no allocs) -------------
__device__ float    g_h[BATCH*NH*NN*FH];     // head projections [b][h][n][64]
__device__ float    g_f1[BATCH*NH*NN];
__device__ float    g_f2[BATCH*NH*NN];
__device__ unsigned g_adjbits[BATCH*NN*16];  // 512 bits per row
__device__ float    g_xcat[BATCH*NN*NH*FH];  // layer-1 output [b][n][512]
__device__ float    g_h2[BATCH*NN*NC];       // output projection
__device__ float    g_f1o[BATCH*NN];
__device__ float    g_f2o[BATCH*NN];

// ------------------------- helpers -----------------------------------------
__device__ __forceinline__ float to_tf32(float v) {
    uint32_t b;
    asm("cvt.rna.tf32.f32 %0, %1;" : "=r"(b) : "f"(v));
    return __uint_as_float(b);
}
__device__ __forceinline__ uint32_t tf32_bits(float v) {
    uint32_t b;
    asm("cvt.rna.tf32.f32 %0, %1;" : "=r"(b) : "f"(v));
    return b;
}
__device__ __forceinline__ uint32_t pk_f16(float hi, float lo) {
    uint32_t w;
    asm("cvt.rn.f16x2.f32 %0, %1, %2;" : "=r"(w) : "f"(hi), "f"(lo));
    return w;   // upper half = hi, lower half = lo
}

__device__ __forceinline__ void mma_tf32(float d[4], const uint32_t a[4], const uint32_t b[2]) {
    asm volatile(
        "mma.sync.aligned.m16n8k8.row.col.f32.tf32.tf32.f32 "
        "{%0,%1,%2,%3}, {%4,%5,%6,%7}, {%8,%9}, {%0,%1,%2,%3};"
        : "+f"(d[0]), "+f"(d[1]), "+f"(d[2]), "+f"(d[3])
        : "r"(a[0]), "r"(a[1]), "r"(a[2]), "r"(a[3]), "r"(b[0]), "r"(b[1]));
}

__device__ __forceinline__ void mma_f16(float d[4], const uint32_t a[4], const uint32_t b[2]) {
    asm volatile(
        "mma.sync.aligned.m16n8k16.row.col.f32.f16.f16.f32 "
        "{%0,%1,%2,%3}, {%4,%5,%6,%7}, {%8,%9}, {%0,%1,%2,%3};"
        : "+f"(d[0]), "+f"(d[1]), "+f"(d[2]), "+f"(d[3])
        : "r"(a[0]), "r"(a[1]), "r"(a[2]), "r"(a[3]), "r"(b[0]), "r"(b[1]));
}

__device__ __forceinline__ void cp_async16(uint32_t saddr, const void* g) {
    asm volatile("cp.async.cg.shared.global [%0], [%1], 16;" :: "r"(saddr), "l"(g));
}
#define CP_COMMIT() asm volatile("cp.async.commit_group;" ::: "memory")
#define CP_WAIT(n)  asm volatile("cp.async.wait_group %0;" :: "n"(n) : "memory")

// ------------------------- kernel 1: adjacency -> bitmask ------------------
__global__ void adjbits_kernel(const int* __restrict__ adj) {
    int w = threadIdx.x >> 5, lane = threadIdx.x & 31;
    int row = blockIdx.x * 8 + w;
    const int* ap = adj + (size_t)row * NN;
    unsigned* op = g_adjbits + row * 16;
#pragma unroll
    for (int it = 0; it < 16; ++it) {
        int v = ap[it * 32 + lane];
        unsigned m = __ballot_sync(0xffffffffu, v > 0);
        if (lane == 0) op[it] = m;
    }
}

// ------------------------- kernel 2: head GEMM (x resident, W pipelined) ---
#define XS_STRIDE 136
#define WS_STRIDE 72
#define GH_WS_OFF  (64*XS_STRIDE)                  // floats
#define GH_RED_OFF (GH_WS_OFF + 2*128*WS_STRIDE)   // floats
#define GH_SMEM ((GH_RED_OFF + 256) * 4)

__global__ void __launch_bounds__(256) gemm_heads(const float* __restrict__ x,
                                                  const float* __restrict__ Wh,
                                                  const float* __restrict__ a1,
                                                  const float* __restrict__ a2) {
    extern __shared__ float sm[];
    float* xs = sm;                    // [64][136] raw fp32
    float* Wsb[2] = { sm + GH_WS_OFF, sm + GH_WS_OFF + 128 * WS_STRIDE };
    float* sred = sm + GH_RED_OFF;     // [64][2 nt-halves][2]
    int b = blockIdx.y;
    int n0 = blockIdx.x * 64;
    int t = threadIdx.x;
    uint32_t xs_u  = (uint32_t)__cvta_generic_to_shared(xs);
    uint32_t ws_u[2] = { (uint32_t)__cvta_generic_to_shared(Wsb[0]),
                         (uint32_t)__cvta_generic_to_shared(Wsb[1]) };

    // group0: x tile + W(head 0)
    const float4* xp4 = (const float4*)(x + ((size_t)b * NN + n0) * NF);
    for (int idx = t; idx < 64 * 32; idx += 256) {
        int r = idx >> 5, c4 = idx & 31;
        cp_async16(xs_u + (r * XS_STRIDE + c4 * 4) * 4, xp4 + idx);
    }
    const float4* Wp4 = (const float4*)Wh;   // [NH][128][16] float4
    for (int idx = t; idx < 128 * 16; idx += 256) {
        int f = idx >> 4, o4 = idx & 15;
        cp_async16(ws_u[0] + (f * WS_STRIDE + o4 * 4) * 4, Wp4 + idx);
    }
    CP_COMMIT();

    int w = t >> 5, lane = t & 31;
    int gid = lane >> 2, tig = lane & 3;
    int mt = w >> 1;
    int nbase = (w & 1) * 32;

#pragma unroll 1
    for (int head = 0; head < NH; ++head) {
        int buf = head & 1;
        if (head < NH - 1) {
            const float4* Wn = Wp4 + (size_t)(head + 1) * 128 * 16;
            for (int idx = t; idx < 128 * 16; idx += 256) {
                int f = idx >> 4, o4 = idx & 15;
                cp_async16(ws_u[buf ^ 1] + (f * WS_STRIDE + o4 * 4) * 4, Wn + idx);
            }
            CP_COMMIT();
            CP_WAIT(1);
        } else {
            CP_WAIT(0);
        }
        __syncthreads();

        const float* Ws = Wsb[buf];
        float d[4][4] = {};
        uint32_t a[4], bf[2];
#pragma unroll
        for (int kk = 0; kk < 16; ++kk) {
            int k0 = kk * 8;
            const float* pa = xs + (mt * 16 + gid) * XS_STRIDE + k0 + tig;
            a[0] = tf32_bits(pa[0]);
            a[1] = tf32_bits(pa[8 * XS_STRIDE]);
            a[2] = tf32_bits(pa[4]);
            a[3] = tf32_bits(pa[8 * XS_STRIDE + 4]);
#pragma unroll
            for (int nt = 0; nt < 4; ++nt) {
                const float* pb = Ws + (k0 + tig) * WS_STRIDE + nbase + nt * 8 + gid;
                bf[0] = tf32_bits(pb[0]);
                bf[1] = tf32_bits(pb[4 * WS_STRIDE]);
                mma_tf32(d[nt], a, bf);
            }
        }
        float* hp = g_h + (((size_t)b * NH + head) * NN + n0) * FH;
#pragma unroll
        for (int nt = 0; nt < 4; ++nt) {
            int col = nbase + nt * 8 + 2 * tig;
            int r0 = mt * 16 + gid;
            *(float2*)&hp[r0 * FH + col]       = make_float2(d[nt][0], d[nt][1]);
            *(float2*)&hp[(r0 + 8) * FH + col] = make_float2(d[nt][2], d[nt][3]);
        }

        // fused f1/f2
        float s1a = 0.f, s1b = 0.f, s2a = 0.f, s2b = 0.f;
#pragma unroll
        for (int nt = 0; nt < 4; ++nt) {
            int c0 = nbase + nt * 8 + 2 * tig;
            float a1x = __ldg(&a1[head * FH + c0]), a1y = __ldg(&a1[head * FH + c0 + 1]);
            float a2x = __ldg(&a2[head * FH + c0]), a2y = __ldg(&a2[head * FH + c0 + 1]);
            s1a += d[nt][0] * a1x + d[nt][1] * a1y;
            s1b += d[nt][2] * a1x + d[nt][3] * a1y;
            s2a += d[nt][0] * a2x + d[nt][1] * a2y;
            s2b += d[nt][2] * a2x + d[nt][3] * a2y;
        }
#pragma unroll
        for (int o = 1; o <= 2; o <<= 1) {
            s1a += __shfl_xor_sync(0xffffffffu, s1a, o);
            s1b += __shfl_xor_sync(0xffffffffu, s1b, o);
            s2a += __shfl_xor_sync(0xffffffffu, s2a, o);
            s2b += __shfl_xor_sync(0xffffffffu, s2b, o);
        }
        if (tig == 0) {
            int rl = mt * 16 + gid, hh = w & 1;
            sred[(rl)     * 4 + hh * 2 + 0] = s1a;
            sred[(rl)     * 4 + hh * 2 + 1] = s2a;
            sred[(rl + 8) * 4 + hh * 2 + 0] = s1b;
            sred[(rl + 8) * 4 + hh * 2 + 1] = s2b;
        }
        __syncthreads();
        if (t < 64) {
            int gi = (b * NH + head) * NN + n0 + t;
            g_f1[gi] = sred[t * 4 + 0] + sred[t * 4 + 2];
            g_f2[gi] = sred[t * 4 + 1] + sred[t * 4 + 3];
        }
    }
}

// ------------------------- kernel 3: attn layer 1 (fp16 m16n8k16 MMA) ------
// h packed fp16x2 over adjacent k-rows: hw[j/2][c] = {hi=h[j+1][c], lo=h[j][c]}.
// One LDS.32 per B fragment. P computed in fp32, packed to fp16x2 A frags.
// Exp-domain mask compare (y < e^{-f1}); rowsum via consistent ones-column
// fp16 MMA. Half the MMA instructions of the tf32 path at 2x per-inst rate.
#define HW_STRIDE 72                          // words per k-pair row
#define A1_F2Q  (256 * HW_STRIDE * 4)         // 73728 bytes
#define ATTN1_SMEM (A1_F2Q + NN * 8)          // 77824

__global__ void __launch_bounds__(512) attn1_kernel() {
    extern __shared__ __align__(16) char smc[];
    uint32_t* hw   = (uint32_t*)smc;
    float2*   f2q2 = (float2*)(smc + A1_F2Q);

    int t = threadIdx.x, w = t >> 5, lane = t & 31;
    int gid = lane >> 2, tig = lane & 3;
    int blk = blockIdx.x, b = blk >> 3, head = blk & 7;
    const float* hp  = g_h  + (size_t)blk * NN * FH;
    const float* f1p = g_f1 + blk * NN;
    const float* f2p = g_f2 + blk * NN;
    const unsigned* ab = g_adjbits + (size_t)b * NN * 16;

    {   // stage h as fp16x2 adjacent-k pairs
        const float4* hp4 = (const float4*)hp;
        for (int idx = t; idx < 256 * 16; idx += 512) {
            int jp = idx >> 4, c4 = idx & 15;
            float4 lo4 = hp4[(2 * jp) * 16 + c4];
            float4 hi4 = hp4[(2 * jp + 1) * 16 + c4];
            uint4 wv;
            wv.x = pk_f16(hi4.x, lo4.x);
            wv.y = pk_f16(hi4.y, lo4.y);
            wv.z = pk_f16(hi4.z, lo4.z);
            wv.w = pk_f16(hi4.w, lo4.w);
            *(uint4*)&hw[jp * HW_STRIDE + c4 * 4] = wv;
        }
        for (int i = t; i < NN; i += 512) {
            float f2 = f2p[i];
            f2q2[i] = make_float2(__expf(f2), __expf(0.2f * f2));
        }
    }
    __syncthreads();

    const uint32_t ONE16 = 0x3C003C00u;

#pragma unroll
    for (int iter = 0; iter < 2; ++iter) {
        int r0 = (iter * 16 + w) * 16;
        int ra = r0 + gid, rb = ra + 8;
        float f1a = __ldg(&f1p[ra]), f1b = __ldg(&f1p[rb]);
        float Ea = __expf(f1a), Ean = __expf(0.2f * f1a), EinvA = __expf(-f1a);
        float Eb = __expf(f1b), Ebn = __expf(0.2f * f1b), EinvB = __expf(-f1b);
        const unsigned* ma = &ab[(size_t)ra * 16];
        const unsigned* mb = &ab[(size_t)rb * 16];

        float d[9][4];
#pragma unroll
        for (int nt = 0; nt < 9; ++nt)
#pragma unroll
            for (int u = 0; u < 4; ++u) d[nt][u] = 0.f;

        for (int kw = 0; kw < 16; ++kw) {
            unsigned wa = __ldg(&ma[kw]);
            unsigned wb = __ldg(&mb[kw]);
#pragma unroll
            for (int hf = 0; hf < 2; ++hf) {
                int k0 = kw * 32 + hf * 16;
                unsigned w0 = wa >> (hf * 16 + 2 * tig);
                unsigned w1 = wb >> (hf * 16 + 2 * tig);
                // {yA,zA,yB,zB} for k = k0+2tig, k0+2tig+1 ; same +8
                float4 v1 = *(const float4*)&f2q2[k0 + 2 * tig];
                float4 v2 = *(const float4*)&f2q2[k0 + 2 * tig + 8];

                float paA = (v1.x < EinvA) ? Ean * v1.y : Ea * v1.x;
                paA = (w0 & 1u) ? paA : 0.f;
                float paB = (v1.z < EinvA) ? Ean * v1.w : Ea * v1.z;
                paB = ((w0 >> 1) & 1u) ? paB : 0.f;
                float paC = (v2.x < EinvA) ? Ean * v2.y : Ea * v2.x;
                paC = ((w0 >> 8) & 1u) ? paC : 0.f;
                float paD = (v2.z < EinvA) ? Ean * v2.w : Ea * v2.z;
                paD = ((w0 >> 9) & 1u) ? paD : 0.f;

                float pbA = (v1.x < EinvB) ? Ebn * v1.y : Eb * v1.x;
                pbA = (w1 & 1u) ? pbA : 0.f;
                float pbB = (v1.z < EinvB) ? Ebn * v1.w : Eb * v1.z;
                pbB = ((w1 >> 1) & 1u) ? pbB : 0.f;
                float pbC = (v2.x < EinvB) ? Ebn * v2.y : Eb * v2.x;
                pbC = ((w1 >> 8) & 1u) ? pbC : 0.f;
                float pbD = (v2.z < EinvB) ? Ebn * v2.w : Eb * v2.z;
                pbD = ((w1 >> 9) & 1u) ? pbD : 0.f;

                uint32_t a[4];
                a[0] = pk_f16(paB, paA);   // row ra, k 2tig,2tig+1
                a[1] = pk_f16(pbB, pbA);   // row rb
                a[2] = pk_f16(paD, paC);   // row ra, k +8
                a[3] = pk_f16(pbD, pbC);   // row rb, k +8

                const uint32_t* pw = hw + (kw * 16 + hf * 8 + tig) * HW_STRIDE + gid;
#pragma unroll
                for (int nt = 0; nt < 8; ++nt) {
                    uint32_t bf[2];
                    bf[0] = pw[nt * 8];
                    bf[1] = pw[4 * HW_STRIDE + nt * 8];
                    mma_f16(d[nt], a, bf);
                }
                {   // ones column: exact row sums of the fp16 P values
                    uint32_t bf[2] = {ONE16, ONE16};
                    mma_f16(d[8], a, bf);
                }
            }
        }

        float inv0 = 1.f / d[8][0], inv1 = 1.f / d[8][2];

        float* oa = g_xcat + ((size_t)b * NN + ra) * (NH * FH) + head * FH;
        float* ob = g_xcat + ((size_t)b * NN + rb) * (NH * FH) + head * FH;
#pragma unroll
        for (int nt = 0; nt < 8; ++nt) {
            float v0 = d[nt][0] * inv0, v1 = d[nt][1] * inv0;
            v0 = v0 > 0.f ? v0 : (__expf(v0) - 1.f);
            v1 = v1 > 0.f ? v1 : (__expf(v1) - 1.f);
            *(float2*)&oa[nt * 8 + 2 * tig] = make_float2(v0, v1);
            float v2 = d[nt][2] * inv1, v3 = d[nt][3] * inv1;
            v2 = v2 > 0.f ? v2 : (__expf(v2) - 1.f);
            v3 = v3 > 0.f ? v3 : (__expf(v3) - 1.f);
            *(float2*)&ob[nt * 8 + 2 * tig] = make_float2(v2, v3);
        }
    }
}

// ------------------------- kernel 4: output GEMM (3-buf pipeline) ----------
#define GO_WS_STRIDE 24
#define GO_XS_STRIDE 68
#define GO_XS_OFF  (512 * GO_WS_STRIDE)                       // floats
#define GO_RED_OFF (GO_XS_OFF + 3 * 64 * GO_XS_STRIDE)        // floats
#define GO_SMEM ((GO_RED_OFF + 256) * 4)

__global__ void __launch_bounds__(256) gemm_out(const float* __restrict__ Wout,
                                                const float* __restrict__ a1o,
                                                const float* __restrict__ a2o) {
    extern __shared__ float sm[];
    float* Ws = sm;                                   // [512][24]
    float* xsb[3] = { sm + GO_XS_OFF,
                      sm + GO_XS_OFF + 64 * GO_XS_STRIDE,
                      sm + GO_XS_OFF + 2 * 64 * GO_XS_STRIDE };
    float* sred = sm + GO_RED_OFF;
    int b = blockIdx.x, rt = blockIdx.y;
    int t = threadIdx.x, w = t >> 5, lane = t & 31;
    int gid = lane >> 2, tig = lane & 3;
    uint32_t ws_u = (uint32_t)__cvta_generic_to_shared(Ws);
    uint32_t xs_u[3] = { (uint32_t)__cvta_generic_to_shared(xsb[0]),
                         (uint32_t)__cvta_generic_to_shared(xsb[1]),
                         (uint32_t)__cvta_generic_to_shared(xsb[2]) };

    const float4* Wo4 = (const float4*)Wout;          // [512][4] float4
    const float4* xp4 = (const float4*)(g_xcat + ((size_t)b * NN + rt * 64) * 512);

    // group0: W + chunk0 ; group1: chunk1
    for (int idx = t; idx < 512 * 4; idx += 256) {
        int k = idx >> 2, c4 = idx & 3;
        cp_async16(ws_u + (k * GO_WS_STRIDE + c4 * 4) * 4, Wo4 + idx);
    }
    for (int idx = t; idx < 64 * 16; idx += 256) {
        int r = idx >> 4, c4 = idx & 15;
        cp_async16(xs_u[0] + (r * GO_XS_STRIDE + c4 * 4) * 4, xp4 + r * 128 + c4);
    }
    CP_COMMIT();
    for (int idx = t; idx < 64 * 16; idx += 256) {
        int r = idx >> 4, c4 = idx & 15;
        cp_async16(xs_u[1] + (r * GO_XS_STRIDE + c4 * 4) * 4, xp4 + r * 128 + 16 + c4);
    }
    CP_COMMIT();

    int mt = w >> 1, ntile = w & 1;
    float d[4] = {};
    uint32_t a[4], bf[2];

#pragma unroll 1
    for (int ch = 0; ch < 8; ++ch) {
        if (ch < 7) { CP_WAIT(1); } else { CP_WAIT(0); }
        __syncthreads();
        const float* xs = xsb[ch % 3];
#pragma unroll
        for (int ks = 0; ks < 8; ++ks) {
            int k0 = ks * 8;
            const float* pa = xs + (mt * 16 + gid) * GO_XS_STRIDE + k0 + tig;
            a[0] = tf32_bits(pa[0]);
            a[1] = tf32_bits(pa[8 * GO_XS_STRIDE]);
            a[2] = tf32_bits(pa[4]);
            a[3] = tf32_bits(pa[8 * GO_XS_STRIDE + 4]);
            const float* pb = Ws + (ch * 64 + k0 + tig) * GO_WS_STRIDE + ntile * 8 + gid;
            bf[0] = tf32_bits(pb[0]);
            bf[1] = tf32_bits(pb[4 * GO_WS_STRIDE]);
            mma_tf32(d, a, bf);
        }
        if (ch + 2 < 8) {
            int tb = (ch + 2) % 3;
            for (int idx = t; idx < 64 * 16; idx += 256) {
                int r = idx >> 4, c4 = idx & 15;
                cp_async16(xs_u[tb] + (r * GO_XS_STRIDE + c4 * 4) * 4,
                           xp4 + r * 128 + (ch + 2) * 16 + c4);
            }
            CP_COMMIT();
        }
    }

    // write h2 + fused f1o/f2o (cross-warp combine of the two n-tiles)
    int ra = rt * 64 + mt * 16 + gid, rb = ra + 8;
    int c0 = ntile * 8 + 2 * tig;
    *(float2*)&g_h2[((size_t)b * NN + ra) * NC + c0] = make_float2(d[0], d[1]);
    *(float2*)&g_h2[((size_t)b * NN + rb) * NC + c0] = make_float2(d[2], d[3]);

    float a1x = __ldg(&a1o[c0]), a1y = __ldg(&a1o[c0 + 1]);
    float a2x = __ldg(&a2o[c0]), a2y = __ldg(&a2o[c0 + 1]);
    float s1a = d[0] * a1x + d[1] * a1y;
    float s1b = d[2] * a1x + d[3] * a1y;
    float s2a = d[0] * a2x + d[1] * a2y;
    float s2b = d[2] * a2x + d[3] * a2y;
#pragma unroll
    for (int o = 1; o <= 2; o <<= 1) {
        s1a += __shfl_xor_sync(0xffffffffu, s1a, o);
        s1b += __shfl_xor_sync(0xffffffffu, s1b, o);
        s2a += __shfl_xor_sync(0xffffffffu, s2a, o);
        s2b += __shfl_xor_sync(0xffffffffu, s2b, o);
    }
    if (tig == 0) {
        int rl = mt * 16 + gid;
        sred[(rl)     * 4 + ntile * 2 + 0] = s1a;
        sred[(rl)     * 4 + ntile * 2 + 1] = s2a;
        sred[(rl + 8) * 4 + ntile * 2 + 0] = s1b;
        sred[(rl + 8) * 4 + ntile * 2 + 1] = s2b;
    }
    __syncthreads();
    if (t < 64) {
        g_f1o[b * NN + rt * 64 + t] = sred[t * 4 + 0] + sred[t * 4 + 2];
        g_f2o[b * NN + rt * 64 + t] = sred[t * 4 + 1] + sred[t * 4 + 3];
    }
}

// ------------------------- kernel 5: output attention (register-P MMA) -----
#define O_F2Q 32768
#define ATTN2_SMEM (O_F2Q + 8192)
__global__ void __launch_bounds__(256) attn_out(float* __restrict__ out_l2) {
    extern __shared__ __align__(16) char sm2[];
    float*  hs  = (float*)sm2;             // [512][16] swizzled
    float4* f2q = (float4*)(sm2 + O_F2Q);  // [512]

    int b = blockIdx.y, rbase = blockIdx.x * 128;
    const float* hp  = g_h2  + (size_t)b * NN * NC;
    const float* f1p = g_f1o + b * NN;
    const float* f2p = g_f2o + b * NN;
    const unsigned* ab = g_adjbits + (size_t)b * NN * 16;

    int t = threadIdx.x, w = t >> 5, lane = t & 31;
    int gid = lane >> 2, tig = lane & 3;

    for (int idx = t; idx < NN * NC; idx += 256) {
        int j = idx >> 4, c = idx & 15;
        hs[j * 16 + ((c + 4 * (j & 3)) & 15)] = to_tf32(hp[idx]);
    }
    for (int i = t; i < NN; i += 256) {
        float f2 = f2p[i];
        f2q[i] = make_float4(f2, __expf(f2), __expf(0.2f * f2), 0.f);
    }
    __syncthreads();

    const uint32_t ONE = 0x3f800000u;

    int ra = rbase + w * 16 + gid, rb = ra + 8;
    float f1a = __ldg(&f1p[ra]), f1b = __ldg(&f1p[rb]);
    float Ea = __expf(f1a), Ean = __expf(0.2f * f1a), nfa = -f1a;
    float Eb = __expf(f1b), Ebn = __expf(0.2f * f1b), nfb = -f1b;
    const unsigned* ma = &ab[(size_t)ra * 16];
    const unsigned* mb = &ab[(size_t)rb * 16];
    int c0 = (gid + 4 * tig) & 15;           // swizzled col for nt=0
    int c1 = (c0 + 8) & 15;                  // swizzled col for nt=1

    float d[3][4] = {};

    for (int kw = 0; kw < 16; ++kw) {
        unsigned wa = __ldg(&ma[kw]) >> tig;
        unsigned wb = __ldg(&mb[kw]) >> tig;
#pragma unroll
        for (int ks = 0; ks < 4; ++ks) {
            int k0 = kw * 32 + ks * 8;
            unsigned w0 = wa >> (ks * 8);
            unsigned w1 = wb >> (ks * 8);
            float4 q0 = f2q[k0 + tig];
            float4 q1 = f2q[k0 + tig + 4];

            float pa0 = (q0.x < nfa) ? Ean * q0.z : Ea * q0.y;
            pa0 = (w0 & 1u) ? pa0 : 0.f;
            float pb0 = (q0.x < nfb) ? Ebn * q0.z : Eb * q0.y;
            pb0 = (w1 & 1u) ? pb0 : 0.f;
            float pa1 = (q1.x < nfa) ? Ean * q1.z : Ea * q1.y;
            pa1 = ((w0 >> 4) & 1u) ? pa1 : 0.f;
            float pb1 = (q1.x < nfb) ? Ebn * q1.z : Eb * q1.y;
            pb1 = ((w1 >> 4) & 1u) ? pb1 : 0.f;

            uint32_t a[4];
            a[0] = __float_as_uint(pa0);
            a[1] = __float_as_uint(pb0);
            a[2] = __float_as_uint(pa1);
            a[3] = __float_as_uint(pb1);

            const float* pb0p = hs + (k0 + tig) * 16;
            const float* pb1p = hs + (k0 + tig + 4) * 16;
            uint32_t bf[2];
            bf[0] = __float_as_uint(pb0p[c0]);
            bf[1] = __float_as_uint(pb1p[c0]);
            mma_tf32(d[0], a, bf);
            bf[0] = __float_as_uint(pb0p[c1]);
            bf[1] = __float_as_uint(pb1p[c1]);
            mma_tf32(d[1], a, bf);
            bf[0] = ONE; bf[1] = ONE;
            mma_tf32(d[2], a, bf);
        }
    }

    float inv0 = 1.f / d[2][0], inv1 = 1.f / d[2][2];

    float* oa = out_l2 + ((size_t)b * NN + ra) * NC;
    float* ob = out_l2 + ((size_t)b * NN + rb) * NC;
#pragma unroll
    for (int nt = 0; nt < 2; ++nt) {
        *(float2*)&oa[nt * 8 + 2 * tig] = make_float2(d[nt][0] * inv0, d[nt][1] * inv0);
        *(float2*)&ob[nt * 8 + 2 * tig] = make_float2(d[nt][2] * inv1, d[nt][3] * inv1);
    }
}

// ------------------------- launch ------------------------------------------
extern "C" void kernel_launch(void* const* d_in, const int* in_sizes, int n_in,
                              void* d_out, int out_size) {
    const float* x    = (const float*)d_in[0];
    const int*   adj  = (const int*)  d_in[1];
    const float* Wh   = (const float*)d_in[2];
    const float* a1h  = (const float*)d_in[3];
    const float* a2h  = (const float*)d_in[4];
    const float* Wout = (const float*)d_in[5];
    const float* a1o  = (const float*)d_in[6];
    const float* a2o  = (const float*)d_in[7];
    float* out = (float*)d_out;

    cudaFuncSetAttribute(gemm_heads, cudaFuncAttributeMaxDynamicSharedMemorySize, GH_SMEM);
    cudaFuncSetAttribute(attn1_kernel, cudaFuncAttributeMaxDynamicSharedMemorySize, ATTN1_SMEM);
    cudaFuncSetAttribute(gemm_out, cudaFuncAttributeMaxDynamicSharedMemorySize, GO_SMEM);
    cudaFuncSetAttribute(attn_out, cudaFuncAttributeMaxDynamicSharedMemorySize, ATTN2_SMEM);

    adjbits_kernel<<<BATCH * NN / 8, 256>>>(adj);
    gemm_heads<<<dim3(8, BATCH), 256, GH_SMEM>>>(x, Wh, a1h, a2h);
    attn1_kernel<<<BH, 512, ATTN1_SMEM>>>();
    gemm_out<<<dim3(BATCH, 8), 256, GO_SMEM>>>(Wout, a1o, a2o);
    attn_out<<<dim3(4, BATCH), 256, ATTN2_SMEM>>>(out);
}

// round 16
// speedup vs baseline: 1.2809x; 1.0113x over previous
#include <cuda_runtime.h>
#include <cuda_bf16.h>
#include <cuda_fp16.h>
#include <cstdint>

// Problem constants
#define BATCH 32
#define NN    512       // nodes
#define NF    128       // input features
#define FH    64        // hidden per head
#define NH    8         // heads
#define NC    16        // classes
#define BH    (BATCH*NH)

// ------------------------- scratch (device globals, no allocs) -------------
__device__ float    g_h[BATCH*NH*NN*FH];     // head projections [b][h][n][64]
__device__ float    g_f1[BATCH*NH*NN];
__device__ float    g_f2[BATCH*NH*NN];
__device__ unsigned g_adjbits[BATCH*NN*16];  // 512 bits per row
__device__ uint32_t g_xcat_h[BATCH*NN*256];  // layer-1 out, fp16x2 pairs [b][n][256]
__device__ float    g_h2[BATCH*NN*NC];       // output projection
__device__ float    g_f1o[BATCH*NN];
__device__ float    g_f2o[BATCH*NN];

// ------------------------- helpers -----------------------------------------
__device__ __forceinline__ float to_tf32(float v) {
    uint32_t b;
    asm("cvt.rna.tf32.f32 %0, %1;" : "=r"(b) : "f"(v));
    return __uint_as_float(b);
}
__device__ __forceinline__ uint32_t tf32_bits(float v) {
    uint32_t b;
    asm("cvt.rna.tf32.f32 %0, %1;" : "=r"(b) : "f"(v));
    return b;
}
__device__ __forceinline__ uint32_t pk_f16(float hi, float lo) {
    uint32_t w;
    asm("cvt.rn.f16x2.f32 %0, %1, %2;" : "=r"(w) : "f"(hi), "f"(lo));
    return w;   // upper half = hi, lower half = lo
}

__device__ __forceinline__ void mma_tf32(float d[4], const uint32_t a[4], const uint32_t b[2]) {
    asm volatile(
        "mma.sync.aligned.m16n8k8.row.col.f32.tf32.tf32.f32 "
        "{%0,%1,%2,%3}, {%4,%5,%6,%7}, {%8,%9}, {%0,%1,%2,%3};"
        : "+f"(d[0]), "+f"(d[1]), "+f"(d[2]), "+f"(d[3])
        : "r"(a[0]), "r"(a[1]), "r"(a[2]), "r"(a[3]), "r"(b[0]), "r"(b[1]));
}

__device__ __forceinline__ void mma_f16(float d[4], const uint32_t a[4], const uint32_t b[2]) {
    asm volatile(
        "mma.sync.aligned.m16n8k16.row.col.f32.f16.f16.f32 "
        "{%0,%1,%2,%3}, {%4,%5,%6,%7}, {%8,%9}, {%0,%1,%2,%3};"
        : "+f"(d[0]), "+f"(d[1]), "+f"(d[2]), "+f"(d[3])
        : "r"(a[0]), "r"(a[1]), "r"(a[2]), "r"(a[3]), "r"(b[0]), "r"(b[1]));
}

__device__ __forceinline__ void cp_async16(uint32_t saddr, const void* g) {
    asm volatile("cp.async.cg.shared.global [%0], [%1], 16;" :: "r"(saddr), "l"(g));
}
#define CP_COMMIT() asm volatile("cp.async.commit_group;" ::: "memory")
#define CP_WAIT(n)  asm volatile("cp.async.wait_group %0;" :: "n"(n) : "memory")

// ------------------------- kernel 1: adjacency -> bitmask ------------------
__global__ void adjbits_kernel(const int* __restrict__ adj) {
    int w = threadIdx.x >> 5, lane = threadIdx.x & 31;
    int row = blockIdx.x * 8 + w;
    const int* ap = adj + (size_t)row * NN;
    unsigned* op = g_adjbits + row * 16;
#pragma unroll
    for (int it = 0; it < 16; ++it) {
        int v = ap[it * 32 + lane];
        unsigned m = __ballot_sync(0xffffffffu, v > 0);
        if (lane == 0) op[it] = m;
    }
}

// ------------------------- kernel 2: head GEMM (x resident, W pipelined) ---
#define XS_STRIDE 136
#define WS_STRIDE 72
#define GH_WS_OFF  (64*XS_STRIDE)                  // floats
#define GH_RED_OFF (GH_WS_OFF + 2*128*WS_STRIDE)   // floats
#define GH_SMEM ((GH_RED_OFF + 256) * 4)

__global__ void __launch_bounds__(256) gemm_heads(const float* __restrict__ x,
                                                  const float* __restrict__ Wh,
                                                  const float* __restrict__ a1,
                                                  const float* __restrict__ a2) {
    extern __shared__ float sm[];
    float* xs = sm;                    // [64][136] raw fp32
    float* Wsb[2] = { sm + GH_WS_OFF, sm + GH_WS_OFF + 128 * WS_STRIDE };
    float* sred = sm + GH_RED_OFF;     // [64][2 nt-halves][2]
    int b = blockIdx.y;
    int n0 = blockIdx.x * 64;
    int t = threadIdx.x;
    uint32_t xs_u  = (uint32_t)__cvta_generic_to_shared(xs);
    uint32_t ws_u[2] = { (uint32_t)__cvta_generic_to_shared(Wsb[0]),
                         (uint32_t)__cvta_generic_to_shared(Wsb[1]) };

    // group0: x tile + W(head 0)
    const float4* xp4 = (const float4*)(x + ((size_t)b * NN + n0) * NF);
    for (int idx = t; idx < 64 * 32; idx += 256) {
        int r = idx >> 5, c4 = idx & 31;
        cp_async16(xs_u + (r * XS_STRIDE + c4 * 4) * 4, xp4 + idx);
    }
    const float4* Wp4 = (const float4*)Wh;   // [NH][128][16] float4
    for (int idx = t; idx < 128 * 16; idx += 256) {
        int f = idx >> 4, o4 = idx & 15;
        cp_async16(ws_u[0] + (f * WS_STRIDE + o4 * 4) * 4, Wp4 + idx);
    }
    CP_COMMIT();

    int w = t >> 5, lane = t & 31;
    int gid = lane >> 2, tig = lane & 3;
    int mt = w >> 1;
    int nbase = (w & 1) * 32;

#pragma unroll 1
    for (int head = 0; head < NH; ++head) {
        int buf = head & 1;
        if (head < NH - 1) {
            const float4* Wn = Wp4 + (size_t)(head + 1) * 128 * 16;
            for (int idx = t; idx < 128 * 16; idx += 256) {
                int f = idx >> 4, o4 = idx & 15;
                cp_async16(ws_u[buf ^ 1] + (f * WS_STRIDE + o4 * 4) * 4, Wn + idx);
            }
            CP_COMMIT();
            CP_WAIT(1);
        } else {
            CP_WAIT(0);
        }
        __syncthreads();

        const float* Ws = Wsb[buf];
        float d[4][4] = {};
        uint32_t a[4], bf[2];
#pragma unroll
        for (int kk = 0; kk < 16; ++kk) {
            int k0 = kk * 8;
            const float* pa = xs + (mt * 16 + gid) * XS_STRIDE + k0 + tig;
            a[0] = tf32_bits(pa[0]);
            a[1] = tf32_bits(pa[8 * XS_STRIDE]);
            a[2] = tf32_bits(pa[4]);
            a[3] = tf32_bits(pa[8 * XS_STRIDE + 4]);
#pragma unroll
            for (int nt = 0; nt < 4; ++nt) {
                const float* pb = Ws + (k0 + tig) * WS_STRIDE + nbase + nt * 8 + gid;
                bf[0] = tf32_bits(pb[0]);
                bf[1] = tf32_bits(pb[4 * WS_STRIDE]);
                mma_tf32(d[nt], a, bf);
            }
        }
        float* hp = g_h + (((size_t)b * NH + head) * NN + n0) * FH;
#pragma unroll
        for (int nt = 0; nt < 4; ++nt) {
            int col = nbase + nt * 8 + 2 * tig;
            int r0 = mt * 16 + gid;
            *(float2*)&hp[r0 * FH + col]       = make_float2(d[nt][0], d[nt][1]);
            *(float2*)&hp[(r0 + 8) * FH + col] = make_float2(d[nt][2], d[nt][3]);
        }

        // fused f1/f2
        float s1a = 0.f, s1b = 0.f, s2a = 0.f, s2b = 0.f;
#pragma unroll
        for (int nt = 0; nt < 4; ++nt) {
            int c0 = nbase + nt * 8 + 2 * tig;
            float a1x = __ldg(&a1[head * FH + c0]), a1y = __ldg(&a1[head * FH + c0 + 1]);
            float a2x = __ldg(&a2[head * FH + c0]), a2y = __ldg(&a2[head * FH + c0 + 1]);
            s1a += d[nt][0] * a1x + d[nt][1] * a1y;
            s1b += d[nt][2] * a1x + d[nt][3] * a1y;
            s2a += d[nt][0] * a2x + d[nt][1] * a2y;
            s2b += d[nt][2] * a2x + d[nt][3] * a2y;
        }
#pragma unroll
        for (int o = 1; o <= 2; o <<= 1) {
            s1a += __shfl_xor_sync(0xffffffffu, s1a, o);
            s1b += __shfl_xor_sync(0xffffffffu, s1b, o);
            s2a += __shfl_xor_sync(0xffffffffu, s2a, o);
            s2b += __shfl_xor_sync(0xffffffffu, s2b, o);
        }
        if (tig == 0) {
            int rl = mt * 16 + gid, hh = w & 1;
            sred[(rl)     * 4 + hh * 2 + 0] = s1a;
            sred[(rl)     * 4 + hh * 2 + 1] = s2a;
            sred[(rl + 8) * 4 + hh * 2 + 0] = s1b;
            sred[(rl + 8) * 4 + hh * 2 + 1] = s2b;
        }
        __syncthreads();
        if (t < 64) {
            int gi = (b * NH + head) * NN + n0 + t;
            g_f1[gi] = sred[t * 4 + 0] + sred[t * 4 + 2];
            g_f2[gi] = sred[t * 4 + 1] + sred[t * 4 + 3];
        }
    }
}

// ------------------------- kernel 3: attn layer 1 (fp16 m16n8k16 MMA) ------
#define HW_STRIDE 72                          // words per k-pair row
#define A1_F2Q  (256 * HW_STRIDE * 4)         // 73728 bytes
#define ATTN1_SMEM (A1_F2Q + NN * 8)          // 77824

__global__ void __launch_bounds__(512) attn1_kernel() {
    extern __shared__ __align__(16) char smc[];
    uint32_t* hw   = (uint32_t*)smc;
    float2*   f2q2 = (float2*)(smc + A1_F2Q);

    int t = threadIdx.x, w = t >> 5, lane = t & 31;
    int gid = lane >> 2, tig = lane & 3;
    int blk = blockIdx.x, b = blk >> 3, head = blk & 7;
    const float* hp  = g_h  + (size_t)blk * NN * FH;
    const float* f1p = g_f1 + blk * NN;
    const float* f2p = g_f2 + blk * NN;
    const unsigned* ab = g_adjbits + (size_t)b * NN * 16;

    {   // stage h as fp16x2 adjacent-k pairs
        const float4* hp4 = (const float4*)hp;
        for (int idx = t; idx < 256 * 16; idx += 512) {
            int jp = idx >> 4, c4 = idx & 15;
            float4 lo4 = hp4[(2 * jp) * 16 + c4];
            float4 hi4 = hp4[(2 * jp + 1) * 16 + c4];
            uint4 wv;
            wv.x = pk_f16(hi4.x, lo4.x);
            wv.y = pk_f16(hi4.y, lo4.y);
            wv.z = pk_f16(hi4.z, lo4.z);
            wv.w = pk_f16(hi4.w, lo4.w);
            *(uint4*)&hw[jp * HW_STRIDE + c4 * 4] = wv;
        }
        for (int i = t; i < NN; i += 512) {
            float f2 = f2p[i];
            f2q2[i] = make_float2(__expf(f2), __expf(0.2f * f2));
        }
    }
    __syncthreads();

    const uint32_t ONE16 = 0x3C003C00u;

#pragma unroll
    for (int iter = 0; iter < 2; ++iter) {
        int r0 = (iter * 16 + w) * 16;
        int ra = r0 + gid, rb = ra + 8;
        float f1a = __ldg(&f1p[ra]), f1b = __ldg(&f1p[rb]);
        float Ea = __expf(f1a), Ean = __expf(0.2f * f1a), EinvA = __expf(-f1a);
        float Eb = __expf(f1b), Ebn = __expf(0.2f * f1b), EinvB = __expf(-f1b);
        const unsigned* ma = &ab[(size_t)ra * 16];
        const unsigned* mb = &ab[(size_t)rb * 16];

        float d[9][4];
#pragma unroll
        for (int nt = 0; nt < 9; ++nt)
#pragma unroll
            for (int u = 0; u < 4; ++u) d[nt][u] = 0.f;

        for (int kw = 0; kw < 16; ++kw) {
            unsigned wa = __ldg(&ma[kw]);
            unsigned wb = __ldg(&mb[kw]);
#pragma unroll
            for (int hf = 0; hf < 2; ++hf) {
                int k0 = kw * 32 + hf * 16;
                unsigned w0 = wa >> (hf * 16 + 2 * tig);
                unsigned w1 = wb >> (hf * 16 + 2 * tig);
                float4 v1 = *(const float4*)&f2q2[k0 + 2 * tig];
                float4 v2 = *(const float4*)&f2q2[k0 + 2 * tig + 8];

                float paA = (v1.x < EinvA) ? Ean * v1.y : Ea * v1.x;
                paA = (w0 & 1u) ? paA : 0.f;
                float paB = (v1.z < EinvA) ? Ean * v1.w : Ea * v1.z;
                paB = ((w0 >> 1) & 1u) ? paB : 0.f;
                float paC = (v2.x < EinvA) ? Ean * v2.y : Ea * v2.x;
                paC = ((w0 >> 8) & 1u) ? paC : 0.f;
                float paD = (v2.z < EinvA) ? Ean * v2.w : Ea * v2.z;
                paD = ((w0 >> 9) & 1u) ? paD : 0.f;

                float pbA = (v1.x < EinvB) ? Ebn * v1.y : Eb * v1.x;
                pbA = (w1 & 1u) ? pbA : 0.f;
                float pbB = (v1.z < EinvB) ? Ebn * v1.w : Eb * v1.z;
                pbB = ((w1 >> 1) & 1u) ? pbB : 0.f;
                float pbC = (v2.x < EinvB) ? Ebn * v2.y : Eb * v2.x;
                pbC = ((w1 >> 8) & 1u) ? pbC : 0.f;
                float pbD = (v2.z < EinvB) ? Ebn * v2.w : Eb * v2.z;
                pbD = ((w1 >> 9) & 1u) ? pbD : 0.f;

                uint32_t a[4];
                a[0] = pk_f16(paB, paA);
                a[1] = pk_f16(pbB, pbA);
                a[2] = pk_f16(paD, paC);
                a[3] = pk_f16(pbD, pbC);

                const uint32_t* pw = hw + (kw * 16 + hf * 8 + tig) * HW_STRIDE + gid;
#pragma unroll
                for (int nt = 0; nt < 8; ++nt) {
                    uint32_t bf[2];
                    bf[0] = pw[nt * 8];
                    bf[1] = pw[4 * HW_STRIDE + nt * 8];
                    mma_f16(d[nt], a, bf);
                }
                {
                    uint32_t bf[2] = {ONE16, ONE16};
                    mma_f16(d[8], a, bf);
                }
            }
        }

        float inv0 = 1.f / d[8][0], inv1 = 1.f / d[8][2];

        // write x_cat as fp16 pairs
        uint32_t* oa = g_xcat_h + ((size_t)b * NN + ra) * 256 + head * 32;
        uint32_t* ob = g_xcat_h + ((size_t)b * NN + rb) * 256 + head * 32;
#pragma unroll
        for (int nt = 0; nt < 8; ++nt) {
            float v0 = d[nt][0] * inv0, v1 = d[nt][1] * inv0;
            v0 = v0 > 0.f ? v0 : (__expf(v0) - 1.f);
            v1 = v1 > 0.f ? v1 : (__expf(v1) - 1.f);
            oa[nt * 4 + tig] = pk_f16(v1, v0);
            float v2 = d[nt][2] * inv1, v3 = d[nt][3] * inv1;
            v2 = v2 > 0.f ? v2 : (__expf(v2) - 1.f);
            v3 = v3 > 0.f ? v3 : (__expf(v3) - 1.f);
            ob[nt * 4 + tig] = pk_f16(v3, v2);
        }
    }
}

// ------------------------- kernel 4: output GEMM (fp16, 3-buf pipeline) ----
// x_cat fp16 pairs [row][256 words]; W packed fp16 k-pairs in smem.
#define GO_WS_STRIDE 24                                  // words per k-pair
#define GO_XS_STRIDE 36                                  // words per row chunk
#define GO_XS_OFF  (256 * GO_WS_STRIDE)                  // words
#define GO_RED_OFF (GO_XS_OFF + 3 * 64 * GO_XS_STRIDE)   // words
#define GO_SMEM ((GO_RED_OFF + 256) * 4)

__global__ void __launch_bounds__(256) gemm_out(const float* __restrict__ Wout,
                                                const float* __restrict__ a1o,
                                                const float* __restrict__ a2o) {
    extern __shared__ uint32_t smw[];
    uint32_t* Wsh = smw;                                  // [256 kpairs][24]
    uint32_t* xsb[3] = { smw + GO_XS_OFF,
                         smw + GO_XS_OFF + 64 * GO_XS_STRIDE,
                         smw + GO_XS_OFF + 2 * 64 * GO_XS_STRIDE };
    float* sred = (float*)(smw + GO_RED_OFF);
    int b = blockIdx.x, rt = blockIdx.y;
    int t = threadIdx.x, w = t >> 5, lane = t & 31;
    int gid = lane >> 2, tig = lane & 3;
    uint32_t xs_u[3] = { (uint32_t)__cvta_generic_to_shared(xsb[0]),
                         (uint32_t)__cvta_generic_to_shared(xsb[1]),
                         (uint32_t)__cvta_generic_to_shared(xsb[2]) };

    const uint32_t* xp = g_xcat_h + ((size_t)b * NN + rt * 64) * 256;

    // chunk0 + chunk1 async (8 cp.async16 per row per chunk = 32 words)
    for (int idx = t; idx < 64 * 8; idx += 256) {
        int r = idx >> 3, c4 = idx & 7;
        cp_async16(xs_u[0] + (r * GO_XS_STRIDE + c4 * 4) * 4, xp + r * 256 + c4 * 4);
    }
    CP_COMMIT();
    for (int idx = t; idx < 64 * 8; idx += 256) {
        int r = idx >> 3, c4 = idx & 7;
        cp_async16(xs_u[1] + (r * GO_XS_STRIDE + c4 * 4) * 4, xp + r * 256 + 32 + c4 * 4);
    }
    CP_COMMIT();

    // convert Wout to packed fp16 k-pairs (overlaps async loads)
    for (int idx = t; idx < 256 * 16; idx += 256) {
        int kp = idx >> 4, c = idx & 15;
        Wsh[kp * GO_WS_STRIDE + c] =
            pk_f16(__ldg(&Wout[(2 * kp + 1) * 16 + c]), __ldg(&Wout[2 * kp * 16 + c]));
    }

    int mt = w >> 1, ntile = w & 1;
    float d[4] = {};
    uint32_t a[4], bf[2];

#pragma unroll 1
    for (int ch = 0; ch < 8; ++ch) {
        if (ch < 7) { CP_WAIT(1); } else { CP_WAIT(0); }
        __syncthreads();
        const uint32_t* xs = xsb[ch % 3];
#pragma unroll
        for (int ks = 0; ks < 4; ++ks) {
            int kp0 = ks * 8;
            const uint32_t* pa = xs + (mt * 16 + gid) * GO_XS_STRIDE + kp0 + tig;
            a[0] = pa[0];
            a[1] = pa[8 * GO_XS_STRIDE];
            a[2] = pa[4];
            a[3] = pa[8 * GO_XS_STRIDE + 4];
            const uint32_t* pb = Wsh + (ch * 32 + kp0 + tig) * GO_WS_STRIDE + ntile * 8 + gid;
            bf[0] = pb[0];
            bf[1] = pb[4 * GO_WS_STRIDE];
            mma_f16(d, a, bf);
        }
        if (ch + 2 < 8) {
            int tb = (ch + 2) % 3;
            for (int idx = t; idx < 64 * 8; idx += 256) {
                int r = idx >> 3, c4 = idx & 7;
                cp_async16(xs_u[tb] + (r * GO_XS_STRIDE + c4 * 4) * 4,
                           xp + r * 256 + (ch + 2) * 32 + c4 * 4);
            }
            CP_COMMIT();
        }
    }

    // write h2 + fused f1o/f2o (cross-warp combine of the two n-tiles)
    int ra = rt * 64 + mt * 16 + gid, rb = ra + 8;
    int c0 = ntile * 8 + 2 * tig;
    *(float2*)&g_h2[((size_t)b * NN + ra) * NC + c0] = make_float2(d[0], d[1]);
    *(float2*)&g_h2[((size_t)b * NN + rb) * NC + c0] = make_float2(d[2], d[3]);

    float a1x = __ldg(&a1o[c0]), a1y = __ldg(&a1o[c0 + 1]);
    float a2x = __ldg(&a2o[c0]), a2y = __ldg(&a2o[c0 + 1]);
    float s1a = d[0] * a1x + d[1] * a1y;
    float s1b = d[2] * a1x + d[3] * a1y;
    float s2a = d[0] * a2x + d[1] * a2y;
    float s2b = d[2] * a2x + d[3] * a2y;
#pragma unroll
    for (int o = 1; o <= 2; o <<= 1) {
        s1a += __shfl_xor_sync(0xffffffffu, s1a, o);
        s1b += __shfl_xor_sync(0xffffffffu, s1b, o);
        s2a += __shfl_xor_sync(0xffffffffu, s2a, o);
        s2b += __shfl_xor_sync(0xffffffffu, s2b, o);
    }
    if (tig == 0) {
        int rl = mt * 16 + gid;
        sred[(rl)     * 4 + ntile * 2 + 0] = s1a;
        sred[(rl)     * 4 + ntile * 2 + 1] = s2a;
        sred[(rl + 8) * 4 + ntile * 2 + 0] = s1b;
        sred[(rl + 8) * 4 + ntile * 2 + 1] = s2b;
    }
    __syncthreads();
    if (t < 64) {
        g_f1o[b * NN + rt * 64 + t] = sred[t * 4 + 0] + sred[t * 4 + 2];
        g_f2o[b * NN + rt * 64 + t] = sred[t * 4 + 1] + sred[t * 4 + 3];
    }
}

// ------------------------- kernel 5: output attention (register-P MMA) -----
#define O_F2Q 32768
#define ATTN2_SMEM (O_F2Q + 8192)
__global__ void __launch_bounds__(256) attn_out(float* __restrict__ out_l2) {
    extern __shared__ __align__(16) char sm2[];
    float*  hs  = (float*)sm2;             // [512][16] swizzled
    float4* f2q = (float4*)(sm2 + O_F2Q);  // [512]

    int b = blockIdx.y, rbase = blockIdx.x * 128;
    const float* hp  = g_h2  + (size_t)b * NN * NC;
    const float* f1p = g_f1o + b * NN;
    const float* f2p = g_f2o + b * NN;
    const unsigned* ab = g_adjbits + (size_t)b * NN * 16;

    int t = threadIdx.x, w = t >> 5, lane = t & 31;
    int gid = lane >> 2, tig = lane & 3;

    for (int idx = t; idx < NN * NC; idx += 256) {
        int j = idx >> 4, c = idx & 15;
        hs[j * 16 + ((c + 4 * (j & 3)) & 15)] = to_tf32(hp[idx]);
    }
    for (int i = t; i < NN; i += 256) {
        float f2 = f2p[i];
        f2q[i] = make_float4(f2, __expf(f2), __expf(0.2f * f2), 0.f);
    }
    __syncthreads();

    const uint32_t ONE = 0x3f800000u;

    int ra = rbase + w * 16 + gid, rb = ra + 8;
    float f1a = __ldg(&f1p[ra]), f1b = __ldg(&f1p[rb]);
    float Ea = __expf(f1a), Ean = __expf(0.2f * f1a), nfa = -f1a;
    float Eb = __expf(f1b), Ebn = __expf(0.2f * f1b), nfb = -f1b;
    const unsigned* ma = &ab[(size_t)ra * 16];
    const unsigned* mb = &ab[(size_t)rb * 16];
    int c0 = (gid + 4 * tig) & 15;
    int c1 = (c0 + 8) & 15;

    float d[3][4] = {};

    for (int kw = 0; kw < 16; ++kw) {
        unsigned wa = __ldg(&ma[kw]) >> tig;
        unsigned wb = __ldg(&mb[kw]) >> tig;
#pragma unroll
        for (int ks = 0; ks < 4; ++ks) {
            int k0 = kw * 32 + ks * 8;
            unsigned w0 = wa >> (ks * 8);
            unsigned w1 = wb >> (ks * 8);
            float4 q0 = f2q[k0 + tig];
            float4 q1 = f2q[k0 + tig + 4];

            float pa0 = (q0.x < nfa) ? Ean * q0.z : Ea * q0.y;
            pa0 = (w0 & 1u) ? pa0 : 0.f;
            float pb0 = (q0.x < nfb) ? Ebn * q0.z : Eb * q0.y;
            pb0 = (w1 & 1u) ? pb0 : 0.f;
            float pa1 = (q1.x < nfa) ? Ean * q1.z : Ea * q1.y;
            pa1 = ((w0 >> 4) & 1u) ? pa1 : 0.f;
            float pb1 = (q1.x < nfb) ? Ebn * q1.z : Eb * q1.y;
            pb1 = ((w1 >> 4) & 1u) ? pb1 : 0.f;

            uint32_t a[4];
            a[0] = __float_as_uint(pa0);
            a[1] = __float_as_uint(pb0);
            a[2] = __float_as_uint(pa1);
            a[3] = __float_as_uint(pb1);

            const float* pb0p = hs + (k0 + tig) * 16;
            const float* pb1p = hs + (k0 + tig + 4) * 16;
            uint32_t bf[2];
            bf[0] = __float_as_uint(pb0p[c0]);
            bf[1] = __float_as_uint(pb1p[c0]);
            mma_tf32(d[0], a, bf);
            bf[0] = __float_as_uint(pb0p[c1]);
            bf[1] = __float_as_uint(pb1p[c1]);
            mma_tf32(d[1], a, bf);
            bf[0] = ONE; bf[1] = ONE;
            mma_tf32(d[2], a, bf);
        }
    }

    float inv0 = 1.f / d[2][0], inv1 = 1.f / d[2][2];

    float* oa = out_l2 + ((size_t)b * NN + ra) * NC;
    float* ob = out_l2 + ((size_t)b * NN + rb) * NC;
#pragma unroll
    for (int nt = 0; nt < 2; ++nt) {
        *(float2*)&oa[nt * 8 + 2 * tig] = make_float2(d[nt][0] * inv0, d[nt][1] * inv0);
        *(float2*)&ob[nt * 8 + 2 * tig] = make_float2(d[nt][2] * inv1, d[nt][3] * inv1);
    }
}

// ------------------------- launch ------------------------------------------
extern "C" void kernel_launch(void* const* d_in, const int* in_sizes, int n_in,
                              void* d_out, int out_size) {
    const float* x    = (const float*)d_in[0];
    const int*   adj  = (const int*)  d_in[1];
    const float* Wh   = (const float*)d_in[2];
    const float* a1h  = (const float*)d_in[3];
    const float* a2h  = (const float*)d_in[4];
    const float* Wout = (const float*)d_in[5];
    const float* a1o  = (const float*)d_in[6];
    const float* a2o  = (const float*)d_in[7];
    float* out = (float*)d_out;

    cudaFuncSetAttribute(gemm_heads, cudaFuncAttributeMaxDynamicSharedMemorySize, GH_SMEM);
    cudaFuncSetAttribute(attn1_kernel, cudaFuncAttributeMaxDynamicSharedMemorySize, ATTN1_SMEM);
    cudaFuncSetAttribute(gemm_out, cudaFuncAttributeMaxDynamicSharedMemorySize, GO_SMEM);
    cudaFuncSetAttribute(attn_out, cudaFuncAttributeMaxDynamicSharedMemorySize, ATTN2_SMEM);

    adjbits_kernel<<<BATCH * NN / 8, 256>>>(adj);
    gemm_heads<<<dim3(8, BATCH), 256, GH_SMEM>>>(x, Wh, a1h, a2h);
    attn1_kernel<<<BH, 512, ATTN1_SMEM>>>();
    gemm_out<<<dim3(BATCH, 8), 256, GO_SMEM>>>(Wout, a1o, a2o);
    attn_out<<<dim3(4, BATCH), 256, ATTN2_SMEM>>>(out);
}